// round 9
// baseline (speedup 1.0000x reference)
// Round 9: recurrence synchronized by hardware CGA cluster barriers (8 CTAs = 8 e-slices
// of one head per cluster; DSMEM push + barrier.cluster per step). Replaces the
// hand-rolled L2 spin protocol proven nondeterministic in rounds 5/8.
#include <cuda_runtime.h>
#include <math.h>
#include <stdint.h>

#define BB 4
#define SS 2048
#define DD 1024
#define NH 4
#define DH 256
#define KK 4
#define NSLICE 8

// ---------------- scratch (static device arrays; no allocation) ----------------
__device__ float g_xconv[BB * SS * DD];            // 33.5M floats
__device__ float g_gates[SS * NH * 4 * BB * DH];   // [t][h][g][b][e]
__device__ float g_yout [BB * SS * NH * DH];       // [b][t][h][e]

// ---------------- helpers ----------------
__device__ __forceinline__ float sigmoid_precise(float x) {
    return (float)(1.0 / (1.0 + exp(-(double)x)));
}
__device__ __forceinline__ uint32_t smem_u32(const void* p) {
    uint32_t a;
    asm("{ .reg .u64 t; cvta.to.shared.u64 t, %1; cvt.u32.u64 %0, t; }" : "=r"(a) : "l"(p));
    return a;
}
__device__ __forceinline__ void sts_cluster_f32(uint32_t local_addr, int rank, float v) {
    uint32_t ra;
    asm volatile("mapa.shared::cluster.u32 %0, %1, %2;" : "=r"(ra) : "r"(local_addr), "r"(rank));
    asm volatile("st.shared::cluster.f32 [%0], %1;" :: "r"(ra), "f"(v) : "memory");
}
__device__ __forceinline__ void cluster_sync() {
    asm volatile("barrier.cluster.arrive.aligned;" ::: "memory");
    asm volatile("barrier.cluster.wait.aligned;" ::: "memory");
}

// ---------------- causal depthwise conv (K=4) + swish ----------------
__global__ void conv_swish_k(const float* __restrict__ x,
                             const float* __restrict__ ck,
                             const float* __restrict__ cb) {
    int bs = blockIdx.x;
    int b = bs >> 11, s = bs & (SS - 1);
    int q = threadIdx.x;  // d-quad 0..255
    const float4* x4 = (const float4*)x;
    const float4* k4 = (const float4*)ck;
    float4 k0 = k4[0 * (DD / 4) + q];
    float4 k1 = k4[1 * (DD / 4) + q];
    float4 k2 = k4[2 * (DD / 4) + q];
    float4 k3 = k4[3 * (DD / 4) + q];
    float4 acc = ((const float4*)cb)[q];
    int rowq = (b * SS + s) * (DD / 4);
#define CONV_TAP(kk, kv)                                            \
    { int sr = s - 3 + (kk);                                        \
      if (sr >= 0) {                                                \
          float4 xv = x4[(b * SS + sr) * (DD / 4) + q];             \
          acc.x += (kv).x * xv.x; acc.y += (kv).y * xv.y;           \
          acc.z += (kv).z * xv.z; acc.w += (kv).w * xv.w; } }
    CONV_TAP(0, k0) CONV_TAP(1, k1) CONV_TAP(2, k2) CONV_TAP(3, k3)
#undef CONV_TAP
    float4 r;
    r.x = acc.x * sigmoid_precise(acc.x);
    r.y = acc.y * sigmoid_precise(acc.y);
    r.z = acc.z * sigmoid_precise(acc.z);
    r.w = acc.w * sigmoid_precise(acc.w);
    ((float4*)g_xconv)[rowq + q] = r;
}

// ---------------- gate GEMMs: gates[t][h][g][b][e]  (scalar FMA) ----------------
__global__ void __launch_bounds__(256, 1)
gates_gemm_k(const float* __restrict__ x,
             const float* __restrict__ w_i, const float* __restrict__ w_f,
             const float* __restrict__ w_z, const float* __restrict__ w_o) {
    int h = blockIdx.z >> 2, g = blockIdx.z & 3;
    int b = blockIdx.y >> 1, eh = blockIdx.y & 1;
    int sch = blockIdx.x;
    const float* in = (g < 2) ? g_xconv : x;
    const float* W = (g == 0) ? w_i : (g == 1) ? w_f : (g == 2) ? w_z : w_o;

    int tid = threadIdx.x, lane = tid & 31, wid = tid >> 5;
    int el = wid * 16 + (lane & 15);   // e_local 0..127
    int dh = lane >> 4;                // d-half via lane bit 4
    int eg = eh * 128 + el;            // global e 0..255
    int dbase = dh * 128;

    float w[128];
#pragma unroll
    for (int j = 0; j < 128; j++)
        w[j] = W[(size_t)(h * DH + dbase + j) * DH + eg];

    __shared__ __align__(16) float As[32][256];

    for (int tt = 0; tt < 4; tt++) {
        int s0 = (sch * 4 + tt) * 32;
        for (int l = tid; l < 32 * 64; l += 256) {
            int r = l >> 6, q = l & 63;
            ((float4*)As[r])[q] =
                ((const float4*)(in + (size_t)(b * SS + s0 + r) * DD + h * DH))[q];
        }
        __syncthreads();
#pragma unroll 1
        for (int r = 0; r < 32; r++) {
            float s0a = 0.f, s1a = 0.f, s2a = 0.f, s3a = 0.f;
#pragma unroll
            for (int j = 0; j < 32; j++) {
                float4 av = *(const float4*)&As[r][dbase + 4 * j];
                s0a = fmaf(w[4 * j + 0], av.x, s0a);
                s1a = fmaf(w[4 * j + 1], av.y, s1a);
                s2a = fmaf(w[4 * j + 2], av.z, s2a);
                s3a = fmaf(w[4 * j + 3], av.w, s3a);
            }
            float sum = (s0a + s1a) + (s2a + s3a);
            sum += __shfl_xor_sync(0xffffffffu, sum, 16);
            if (dh == 0)
                g_gates[(size_t)(((s0 + r) * NH + h) * 4 + g) * (BB * DH) + b * DH + eg] = sum;
        }
        __syncthreads();
    }
}

// ---------------- recurrence: clusters of 8 CTAs (one head), DSMEM y exchange ----------------
__global__ void __launch_bounds__(256, 1) __cluster_dims__(NSLICE, 1, 1)
rec_k(const float* __restrict__ Wr, const float* __restrict__ rb) {
    int h = blockIdx.y, si = blockIdx.x;  // si == cluster rank (x dimension)
    int tid = threadIdx.x, lane = tid & 31, wid = tid >> 5;
    int g = wid & 3, ehi = wid >> 2;
    int dh = lane >> 4;
    int e = ehi * 16 + (lane & 15);
    int eg = si * 32 + e;
    int dbase = dh * 128;

    // register-resident recurrent weights: W[h][d][g][eg], d in [dbase, dbase+128)
    float w[128];
#pragma unroll
    for (int j = 0; j < 128; j++)
        w[j] = Wr[(size_t)((h * DH + dbase + j) * 4 + g) * DH + eg];

    // state threads: tid<128 -> (b, e)
    int sb = tid >> 5;
    int se = tid & 31;
    int seg = si * 32 + se;
    float bI = 0, bF = 0, bZ = 0, bO = 0, c = 0, n = 0, m = 0;
    if (tid < 128) {
        bI = rb[(0 * NH + h) * DH + seg];
        bF = rb[(1 * NH + h) * DH + seg];
        bZ = rb[(2 * NH + h) * DH + seg];
        bO = rb[(3 * NH + h) * DH + seg];
    }

    // double-buffered full y (all 256 e, 4 batches), filled by cluster-wide pushes
    __shared__ __align__(16) float y_s[2][BB][DH];
    __shared__ float raw_s[4][BB][32];

    // zero buffer 0 only (buffer 1 is fully overwritten by step-0 pushes)
    for (int i = tid; i < BB * DH / 4; i += 256)
        ((float4*)&y_s[0][0][0])[i] = make_float4(0.f, 0.f, 0.f, 0.f);
    // entry barrier: all CTAs done zeroing before anyone pushes into peers
    cluster_sync();

    // local smem address of my element in each buffer (for cluster stores)
    uint32_t ya0 = 0, ya1 = 0;
    if (tid < 128) {
        ya0 = smem_u32(&y_s[0][sb][seg]);
        ya1 = smem_u32(&y_s[1][sb][seg]);
    }

    for (int t = 0; t < SS; t++) {
        int rd = t & 1;

        // prefetch this step's gate inputs (global loads overlap matvec)
        float gI = 0, gF = 0, gZ = 0, gO = 0;
        if (tid < 128) {
            const float* gp = g_gates + (size_t)(t * NH + h) * 4 * (BB * DH) + sb * DH + seg;
            gI = gp[0];
            gF = gp[BB * DH];
            gZ = gp[2 * BB * DH];
            gO = gp[3 * BB * DH];
        }

        // 4-batch matvec over this thread's 128-d half, reading LOCAL y_s[rd]
        float a0x = 0, a0y = 0, a0z = 0, a0w = 0;
        float a1x = 0, a1y = 0, a1z = 0, a1w = 0;
        float a2x = 0, a2y = 0, a2z = 0, a2w = 0;
        float a3x = 0, a3y = 0, a3z = 0, a3w = 0;
#pragma unroll
        for (int j = 0; j < 32; j++) {
            float w0 = w[4 * j + 0], w1 = w[4 * j + 1], w2 = w[4 * j + 2], w3 = w[4 * j + 3];
            float4 y0 = *(const float4*)&y_s[rd][0][dbase + 4 * j];
            a0x = fmaf(w0, y0.x, a0x); a0y = fmaf(w1, y0.y, a0y);
            a0z = fmaf(w2, y0.z, a0z); a0w = fmaf(w3, y0.w, a0w);
            float4 y1 = *(const float4*)&y_s[rd][1][dbase + 4 * j];
            a1x = fmaf(w0, y1.x, a1x); a1y = fmaf(w1, y1.y, a1y);
            a1z = fmaf(w2, y1.z, a1z); a1w = fmaf(w3, y1.w, a1w);
            float4 y2 = *(const float4*)&y_s[rd][2][dbase + 4 * j];
            a2x = fmaf(w0, y2.x, a2x); a2y = fmaf(w1, y2.y, a2y);
            a2z = fmaf(w2, y2.z, a2z); a2w = fmaf(w3, y2.w, a2w);
            float4 y3 = *(const float4*)&y_s[rd][3][dbase + 4 * j];
            a3x = fmaf(w0, y3.x, a3x); a3y = fmaf(w1, y3.y, a3y);
            a3z = fmaf(w2, y3.z, a3z); a3w = fmaf(w3, y3.w, a3w);
        }
        float r0 = (a0x + a0y) + (a0z + a0w);
        float r1 = (a1x + a1y) + (a1z + a1w);
        float r2 = (a2x + a2y) + (a2z + a2w);
        float r3 = (a3x + a3y) + (a3z + a3w);
        r0 += __shfl_xor_sync(0xffffffffu, r0, 16);
        r1 += __shfl_xor_sync(0xffffffffu, r1, 16);
        r2 += __shfl_xor_sync(0xffffffffu, r2, 16);
        r3 += __shfl_xor_sync(0xffffffffu, r3, 16);
        if (dh == 0) {
            raw_s[g][0][e] = r0;
            raw_s[g][1][e] = r1;
            raw_s[g][2][e] = r2;
            raw_s[g][3][e] = r3;
        }
        __syncthreads();

        if (tid < 128) {
            float rI = raw_s[0][sb][se] + gI + bI;
            float rF = raw_s[1][sb][se] + gF + bF;
            float rZ = raw_s[2][sb][se] + gZ + bZ;
            float rO = raw_s[3][sb][se] + gO + bO;
            // precise log_sigmoid(rF): min(rF,0) - log1p(exp(-|rF|)), DP-evaluated
            float lsf = (float)(fmin((double)rF, 0.0) -
                                log1p(exp(-fabs((double)rF))));
            float lfm = m + lsf;                 // fp32 add (matches jax rounding point)
            float mn = fmaxf(rI, lfm);
            float ig = (float)exp((double)(rI - mn));
            float fg = (float)exp((double)(lfm - mn));
            float tz = (float)tanh((double)rZ);
            c = fg * c + ig * tz;
            n = fg * n + ig;
            m = mn;
            float yv = (float)(((double)c / (double)n) *
                               (1.0 / (1.0 + exp(-(double)rO))));
            // push my y element into buffer rd^1 of EVERY cluster CTA (incl. self)
            uint32_t dst = rd ? ya0 : ya1;
#pragma unroll
            for (int r = 0; r < NSLICE; r++)
                sts_cluster_f32(dst, r, yv);
            g_yout[(size_t)((sb * SS + t) * NH + h) * DH + seg] = yv;
        }
        // hardware release/acquire over the cluster: all pushes visible, all CTAs in step
        cluster_sync();
    }
}

// ---------------- per-head GroupNorm + affine ----------------
__global__ void gnorm_k(const float* __restrict__ gsc,
                        const float* __restrict__ gbi,
                        float* __restrict__ out) {
    int bs = blockIdx.x;
    int b = bs >> 11, s = bs & (SS - 1);
    int lane = threadIdx.x & 31, h = threadIdx.x >> 5;
    const float* yp = g_yout + (size_t)((b * SS + s) * NH + h) * DH;
    float4 v0 = ((const float4*)yp)[lane * 2];
    float4 v1 = ((const float4*)yp)[lane * 2 + 1];
    float sum = v0.x + v0.y + v0.z + v0.w + v1.x + v1.y + v1.z + v1.w;
    float sq = v0.x * v0.x + v0.y * v0.y + v0.z * v0.z + v0.w * v0.w +
               v1.x * v1.x + v1.y * v1.y + v1.z * v1.z + v1.w * v1.w;
#pragma unroll
    for (int o = 16; o; o >>= 1) {
        sum += __shfl_xor_sync(0xffffffffu, sum, o);
        sq += __shfl_xor_sync(0xffffffffu, sq, o);
    }
    float mean = sum * (1.f / DH);
    float var = sq * (1.f / DH) - mean * mean;
    float rs = (float)(1.0 / sqrt((double)var + 1e-6));
    int dbase = h * DH + lane * 8;
    float4 sc0 = ((const float4*)(gsc + dbase))[0];
    float4 sc1 = ((const float4*)(gsc + dbase))[1];
    float4 bi0 = ((const float4*)(gbi + dbase))[0];
    float4 bi1 = ((const float4*)(gbi + dbase))[1];
    float* op = out + (size_t)(b * SS + s) * DD + dbase;
    float4 o0, o1;
    o0.x = (v0.x - mean) * rs * sc0.x + bi0.x;
    o0.y = (v0.y - mean) * rs * sc0.y + bi0.y;
    o0.z = (v0.z - mean) * rs * sc0.z + bi0.z;
    o0.w = (v0.w - mean) * rs * sc0.w + bi0.w;
    o1.x = (v1.x - mean) * rs * sc1.x + bi1.x;
    o1.y = (v1.y - mean) * rs * sc1.y + bi1.y;
    o1.z = (v1.z - mean) * rs * sc1.z + bi1.z;
    o1.w = (v1.w - mean) * rs * sc1.w + bi1.w;
    ((float4*)op)[0] = o0;
    ((float4*)op)[1] = o1;
}

// ---------------- launch ----------------
extern "C" void kernel_launch(void* const* d_in, const int* in_sizes, int n_in,
                              void* d_out, int out_size) {
    const float* x   = (const float*)d_in[0];
    const float* ck  = (const float*)d_in[1];
    const float* cb  = (const float*)d_in[2];
    const float* w_i = (const float*)d_in[3];
    const float* w_f = (const float*)d_in[4];
    const float* w_z = (const float*)d_in[5];
    const float* w_o = (const float*)d_in[6];
    const float* wr  = (const float*)d_in[7];
    const float* rb  = (const float*)d_in[8];
    const float* gsc = (const float*)d_in[9];
    const float* gbi = (const float*)d_in[10];
    float* out = (float*)d_out;

    conv_swish_k<<<BB * SS, 256>>>(x, ck, cb);
    dim3 gg(16, 8, 16);  // x: s-chunks, y: b*2+eh, z: h*4+g
    gates_gemm_k<<<gg, 256>>>(x, w_i, w_f, w_z, w_o);
    dim3 gr(NSLICE, NH);  // clusters of 8 CTAs along x => one cluster per head
    rec_k<<<gr, 256>>>(wr, rb);
    gnorm_k<<<BB * SS, 128>>>(gsc, gbi, out);
}

// round 10
// speedup vs baseline: 1.5238x; 1.5238x over previous
// Round 10: optimize recurrence critical path — packed fma.rn.f32x2 matvec (bit-identical
// reduction tree), fp32 transcendentals (headroom proven by r9's 3.3e-7), split cluster
// arrive/wait to hide barrier latency. Sync architecture unchanged from passing r9.
#include <cuda_runtime.h>
#include <math.h>
#include <stdint.h>

#define BB 4
#define SS 2048
#define DD 1024
#define NH 4
#define DH 256
#define KK 4
#define NSLICE 8

typedef unsigned long long u64;

// ---------------- scratch (static device arrays; no allocation) ----------------
__device__ float g_xconv[BB * SS * DD];            // 33.5M floats
__device__ float g_gates[SS * NH * 4 * BB * DH];   // [t][h][g][b][e]
__device__ float g_yout [BB * SS * NH * DH];       // [b][t][h][e]

// ---------------- helpers ----------------
__device__ __forceinline__ u64 pk2(float a, float b) {
    u64 r; asm("mov.b64 %0,{%1,%2};" : "=l"(r) : "f"(a), "f"(b)); return r;
}
__device__ __forceinline__ u64 f2fma(u64 a, u64 b, u64 c) {
    u64 d; asm("fma.rn.f32x2 %0,%1,%2,%3;" : "=l"(d) : "l"(a), "l"(b), "l"(c)); return d;
}
__device__ __forceinline__ float f2lo(u64 v) { return __uint_as_float((unsigned)v); }
__device__ __forceinline__ float f2hi(u64 v) { return __uint_as_float((unsigned)(v >> 32)); }
__device__ __forceinline__ uint32_t smem_u32(const void* p) {
    uint32_t a;
    asm("{ .reg .u64 t; cvta.to.shared.u64 t, %1; cvt.u32.u64 %0, t; }" : "=r"(a) : "l"(p));
    return a;
}
__device__ __forceinline__ void sts_cluster_f32(uint32_t local_addr, int rank, float v) {
    uint32_t ra;
    asm volatile("mapa.shared::cluster.u32 %0, %1, %2;" : "=r"(ra) : "r"(local_addr), "r"(rank));
    asm volatile("st.shared::cluster.f32 [%0], %1;" :: "r"(ra), "f"(v) : "memory");
}
#define CLUSTER_ARRIVE() asm volatile("barrier.cluster.arrive.aligned;" ::: "memory")
#define CLUSTER_WAIT()   asm volatile("barrier.cluster.wait.aligned;" ::: "memory")

// ---------------- causal depthwise conv (K=4) + swish ----------------
__global__ void conv_swish_k(const float* __restrict__ x,
                             const float* __restrict__ ck,
                             const float* __restrict__ cb) {
    int bs = blockIdx.x;
    int b = bs >> 11, s = bs & (SS - 1);
    int q = threadIdx.x;  // d-quad 0..255
    const float4* x4 = (const float4*)x;
    const float4* k4 = (const float4*)ck;
    float4 k0 = k4[0 * (DD / 4) + q];
    float4 k1 = k4[1 * (DD / 4) + q];
    float4 k2 = k4[2 * (DD / 4) + q];
    float4 k3 = k4[3 * (DD / 4) + q];
    float4 acc = ((const float4*)cb)[q];
    int rowq = (b * SS + s) * (DD / 4);
#define CONV_TAP(kk, kv)                                            \
    { int sr = s - 3 + (kk);                                        \
      if (sr >= 0) {                                                \
          float4 xv = x4[(b * SS + sr) * (DD / 4) + q];             \
          acc.x += (kv).x * xv.x; acc.y += (kv).y * xv.y;           \
          acc.z += (kv).z * xv.z; acc.w += (kv).w * xv.w; } }
    CONV_TAP(0, k0) CONV_TAP(1, k1) CONV_TAP(2, k2) CONV_TAP(3, k3)
#undef CONV_TAP
    float4 r;
    r.x = acc.x / (1.f + expf(-acc.x));
    r.y = acc.y / (1.f + expf(-acc.y));
    r.z = acc.z / (1.f + expf(-acc.z));
    r.w = acc.w / (1.f + expf(-acc.w));
    ((float4*)g_xconv)[rowq + q] = r;
}

// ---------------- gate GEMMs: gates[t][h][g][b][e]  (packed f32x2 FMA) ----------------
__global__ void __launch_bounds__(256, 1)
gates_gemm_k(const float* __restrict__ x,
             const float* __restrict__ w_i, const float* __restrict__ w_f,
             const float* __restrict__ w_z, const float* __restrict__ w_o) {
    int h = blockIdx.z >> 2, g = blockIdx.z & 3;
    int b = blockIdx.y >> 1, eh = blockIdx.y & 1;
    int sch = blockIdx.x;
    const float* in = (g < 2) ? g_xconv : x;
    const float* W = (g == 0) ? w_i : (g == 1) ? w_f : (g == 2) ? w_z : w_o;

    int tid = threadIdx.x, lane = tid & 31, wid = tid >> 5;
    int el = wid * 16 + (lane & 15);   // e_local 0..127
    int dh = lane >> 4;                // d-half via lane bit 4
    int eg = eh * 128 + el;            // global e 0..255
    int dbase = dh * 128;

    // packed weight column: pairs (d, d+1) in lo/hi lanes; stride DH per d
    ulonglong2 wq[32];
#pragma unroll
    for (int j = 0; j < 32; j++) {
        const float* p = W + (size_t)(h * DH + dbase + 4 * j) * DH + eg;
        wq[j].x = pk2(p[0], p[DH]);
        wq[j].y = pk2(p[2 * DH], p[3 * DH]);
    }

    __shared__ __align__(16) float As[32][256];

    for (int tt = 0; tt < 4; tt++) {
        int s0 = (sch * 4 + tt) * 32;
        for (int l = tid; l < 32 * 64; l += 256) {
            int r = l >> 6, q = l & 63;
            ((float4*)As[r])[q] =
                ((const float4*)(in + (size_t)(b * SS + s0 + r) * DD + h * DH))[q];
        }
        __syncthreads();
#pragma unroll 1
        for (int r = 0; r < 32; r++) {
            u64 al = 0, ah = 0;
#pragma unroll
            for (int j = 0; j < 32; j++) {
                ulonglong2 av = *(const ulonglong2*)&As[r][dbase + 4 * j];
                al = f2fma(wq[j].x, av.x, al);
                ah = f2fma(wq[j].y, av.y, ah);
            }
            float sum = (f2lo(al) + f2hi(al)) + (f2lo(ah) + f2hi(ah));
            sum += __shfl_xor_sync(0xffffffffu, sum, 16);
            if (dh == 0)
                g_gates[(size_t)(((s0 + r) * NH + h) * 4 + g) * (BB * DH) + b * DH + eg] = sum;
        }
        __syncthreads();
    }
}

// ---------------- recurrence: clusters of 8 CTAs (one head), DSMEM y exchange ----------------
__global__ void __launch_bounds__(256, 1) __cluster_dims__(NSLICE, 1, 1)
rec_k(const float* __restrict__ Wr, const float* __restrict__ rb) {
    int h = blockIdx.y, si = blockIdx.x;  // si == cluster rank (x dimension)
    int tid = threadIdx.x, lane = tid & 31, wid = tid >> 5;
    int g = wid & 3, ehi = wid >> 2;
    int dh = lane >> 4;
    int e = ehi * 16 + (lane & 15);
    int eg = si * 32 + e;
    int dbase = dh * 128;

    // packed recurrent weights: W[h][d][g][eg], pairs (d, d+1); stride 4*DH per d
    ulonglong2 wq[32];
#pragma unroll
    for (int j = 0; j < 32; j++) {
        const float* p = Wr + (size_t)((h * DH + dbase + 4 * j) * 4 + g) * DH + eg;
        wq[j].x = pk2(p[0], p[4 * DH]);
        wq[j].y = pk2(p[8 * DH], p[12 * DH]);
    }

    // state threads: tid<128 -> (b, e)
    int sb = tid >> 5;
    int se = tid & 31;
    int seg = si * 32 + se;
    float bI = 0, bF = 0, bZ = 0, bO = 0, c = 0, n = 0, m = 0;
    if (tid < 128) {
        bI = rb[(0 * NH + h) * DH + seg];
        bF = rb[(1 * NH + h) * DH + seg];
        bZ = rb[(2 * NH + h) * DH + seg];
        bO = rb[(3 * NH + h) * DH + seg];
    }

    // double-buffered full y (all 256 e, 4 batches), filled by cluster-wide pushes
    __shared__ __align__(16) float y_s[2][BB][DH];
    __shared__ float raw_s[4][BB][32];

    // zero buffer 0 only (buffer 1 is fully overwritten by step-0 pushes)
    for (int i = tid; i < BB * DH / 4; i += 256)
        ((float4*)&y_s[0][0][0])[i] = make_float4(0.f, 0.f, 0.f, 0.f);
    CLUSTER_ARRIVE();  // paired with the wait at top of iteration t=0

    // local smem address of my element in each buffer (for cluster stores)
    uint32_t ya0 = 0, ya1 = 0;
    if (tid < 128) {
        ya0 = smem_u32(&y_s[0][sb][seg]);
        ya1 = smem_u32(&y_s[1][sb][seg]);
    }

    for (int t = 0; t < SS; t++) {
        int rd = t & 1;

        // prefetch this step's gate inputs (global loads issue before barrier wait)
        float gI = 0, gF = 0, gZ = 0, gO = 0;
        if (tid < 128) {
            const float* gp = g_gates + (size_t)(t * NH + h) * 4 * (BB * DH) + sb * DH + seg;
            gI = gp[0];
            gF = gp[BB * DH];
            gZ = gp[2 * BB * DH];
            gO = gp[3 * BB * DH];
        }
        // wait for all cluster pushes into y_s[rd] (paired with previous arrive)
        CLUSTER_WAIT();

        // 4-batch matvec over this thread's 128-d half, packed f32x2, LOCAL y_s[rd]
        u64 a0l = 0, a0h = 0, a1l = 0, a1h = 0, a2l = 0, a2h = 0, a3l = 0, a3h = 0;
#pragma unroll
        for (int j = 0; j < 32; j++) {
            ulonglong2 wv = wq[j];
            ulonglong2 y0 = *(const ulonglong2*)&y_s[rd][0][dbase + 4 * j];
            a0l = f2fma(wv.x, y0.x, a0l); a0h = f2fma(wv.y, y0.y, a0h);
            ulonglong2 y1 = *(const ulonglong2*)&y_s[rd][1][dbase + 4 * j];
            a1l = f2fma(wv.x, y1.x, a1l); a1h = f2fma(wv.y, y1.y, a1h);
            ulonglong2 y2 = *(const ulonglong2*)&y_s[rd][2][dbase + 4 * j];
            a2l = f2fma(wv.x, y2.x, a2l); a2h = f2fma(wv.y, y2.y, a2h);
            ulonglong2 y3 = *(const ulonglong2*)&y_s[rd][3][dbase + 4 * j];
            a3l = f2fma(wv.x, y3.x, a3l); a3h = f2fma(wv.y, y3.y, a3h);
        }
        // same reduction tree as the scalar r9 kernel: (x+y)+(z+w) per batch
        float r0 = (f2lo(a0l) + f2hi(a0l)) + (f2lo(a0h) + f2hi(a0h));
        float r1 = (f2lo(a1l) + f2hi(a1l)) + (f2lo(a1h) + f2hi(a1h));
        float r2 = (f2lo(a2l) + f2hi(a2l)) + (f2lo(a2h) + f2hi(a2h));
        float r3 = (f2lo(a3l) + f2hi(a3l)) + (f2lo(a3h) + f2hi(a3h));
        r0 += __shfl_xor_sync(0xffffffffu, r0, 16);
        r1 += __shfl_xor_sync(0xffffffffu, r1, 16);
        r2 += __shfl_xor_sync(0xffffffffu, r2, 16);
        r3 += __shfl_xor_sync(0xffffffffu, r3, 16);
        if (dh == 0) {
            raw_s[g][0][e] = r0;
            raw_s[g][1][e] = r1;
            raw_s[g][2][e] = r2;
            raw_s[g][3][e] = r3;
        }
        __syncthreads();

        if (tid < 128) {
            float rI = raw_s[0][sb][se] + gI + bI;
            float rF = raw_s[1][sb][se] + gF + bF;
            float rZ = raw_s[2][sb][se] + gZ + bZ;
            float rO = raw_s[3][sb][se] + gO + bO;
            // fp32 stabilized sLSTM update (r9 proved the recurrence is well-conditioned)
            float lsf = fminf(rF, 0.f) - log1pf(expf(-fabsf(rF)));  // log_sigmoid(rF)
            float lfm = m + lsf;
            float mn = fmaxf(rI, lfm);
            float ig = expf(rI - mn);
            float fg = expf(lfm - mn);
            c = fg * c + ig * tanhf(rZ);
            n = fg * n + ig;
            m = mn;
            float yv = (c / n) / (1.f + expf(-rO));
            // push my y element into buffer rd^1 of EVERY cluster CTA (incl. self)
            uint32_t dst = rd ? ya0 : ya1;
#pragma unroll
            for (int r = 0; r < NSLICE; r++)
                sts_cluster_f32(dst, r, yv);
            g_yout[(size_t)((sb * SS + t) * NH + h) * DH + seg] = yv;
        }
        // release: all pushes for step t done; consumed by the wait at top of t+1
        CLUSTER_ARRIVE();
    }
    // balance the final arrive; also guarantees no CTA exits while peers' DSMEM
    // stores targeting this CTA's smem are still in flight
    CLUSTER_WAIT();
}

// ---------------- per-head GroupNorm + affine ----------------
__global__ void gnorm_k(const float* __restrict__ gsc,
                        const float* __restrict__ gbi,
                        float* __restrict__ out) {
    int bs = blockIdx.x;
    int b = bs >> 11, s = bs & (SS - 1);
    int lane = threadIdx.x & 31, h = threadIdx.x >> 5;
    const float* yp = g_yout + (size_t)((b * SS + s) * NH + h) * DH;
    float4 v0 = ((const float4*)yp)[lane * 2];
    float4 v1 = ((const float4*)yp)[lane * 2 + 1];
    float sum = v0.x + v0.y + v0.z + v0.w + v1.x + v1.y + v1.z + v1.w;
    float sq = v0.x * v0.x + v0.y * v0.y + v0.z * v0.z + v0.w * v0.w +
               v1.x * v1.x + v1.y * v1.y + v1.z * v1.z + v1.w * v1.w;
#pragma unroll
    for (int o = 16; o; o >>= 1) {
        sum += __shfl_xor_sync(0xffffffffu, sum, o);
        sq += __shfl_xor_sync(0xffffffffu, sq, o);
    }
    float mean = sum * (1.f / DH);
    float var = sq * (1.f / DH) - mean * mean;
    float rs = rsqrtf(var + 1e-6f);
    int dbase = h * DH + lane * 8;
    float4 sc0 = ((const float4*)(gsc + dbase))[0];
    float4 sc1 = ((const float4*)(gsc + dbase))[1];
    float4 bi0 = ((const float4*)(gbi + dbase))[0];
    float4 bi1 = ((const float4*)(gbi + dbase))[1];
    float* op = out + (size_t)(b * SS + s) * DD + dbase;
    float4 o0, o1;
    o0.x = (v0.x - mean) * rs * sc0.x + bi0.x;
    o0.y = (v0.y - mean) * rs * sc0.y + bi0.y;
    o0.z = (v0.z - mean) * rs * sc0.z + bi0.z;
    o0.w = (v0.w - mean) * rs * sc0.w + bi0.w;
    o1.x = (v1.x - mean) * rs * sc1.x + bi1.x;
    o1.y = (v1.y - mean) * rs * sc1.y + bi1.y;
    o1.z = (v1.z - mean) * rs * sc1.z + bi1.z;
    o1.w = (v1.w - mean) * rs * sc1.w + bi1.w;
    ((float4*)op)[0] = o0;
    ((float4*)op)[1] = o1;
}

// ---------------- launch ----------------
extern "C" void kernel_launch(void* const* d_in, const int* in_sizes, int n_in,
                              void* d_out, int out_size) {
    const float* x   = (const float*)d_in[0];
    const float* ck  = (const float*)d_in[1];
    const float* cb  = (const float*)d_in[2];
    const float* w_i = (const float*)d_in[3];
    const float* w_f = (const float*)d_in[4];
    const float* w_z = (const float*)d_in[5];
    const float* w_o = (const float*)d_in[6];
    const float* wr  = (const float*)d_in[7];
    const float* rb  = (const float*)d_in[8];
    const float* gsc = (const float*)d_in[9];
    const float* gbi = (const float*)d_in[10];
    float* out = (float*)d_out;

    conv_swish_k<<<BB * SS, 256>>>(x, ck, cb);
    dim3 gg(16, 8, 16);  // x: s-chunks, y: b*2+eh, z: h*4+g
    gates_gemm_k<<<gg, 256>>>(x, w_i, w_f, w_z, w_o);
    dim3 gr(NSLICE, NH);  // clusters of 8 CTAs along x => one cluster per head
    rec_k<<<gr, 256>>>(wr, rb);
    gnorm_k<<<BB * SS, 128>>>(gsc, gbi, out);
}